// round 3
// baseline (speedup 1.0000x reference)
#include <cuda_runtime.h>
#include <math.h>

#define B_   4096
#define H_   1024
#define N1_  28
#define N2_  280
#define N3_  2800
#define NTOT (N1_ + N2_ + N3_)   // 3108

// Scratch: sigmoid outputs z = [z1 | z2 | z3], row-major [B_, NTOT]  (~50.9 MB)
__device__ float g_z[(size_t)B_ * NTOT];
// Per-row loss partials (deterministic two-stage reduction, no float atomics)
__device__ float g_loss_rows[B_];

// ---------------------------------------------------------------------------
// GEMM: Z[:, col_off:col_off+N] = sigmoid(x @ W^T + b)
// A = x [B_, H_] row-major, W = [N, H_] row-major (both K-contiguous)
// Classic 128x128x8 SIMT tile, 256 threads, 8x8 register tile per thread.
// ---------------------------------------------------------------------------
#define BM 128
#define BN 128
#define BK 8
#define TM 8
#define TN 8

__device__ __forceinline__ float sigmoidf(float v) {
    return 1.0f / (1.0f + expf(-v));
}

__global__ void __launch_bounds__(256)
gemm_bias_sigmoid(const float* __restrict__ A,
                  const float* __restrict__ W,
                  const float* __restrict__ bias,
                  int N, int col_off)
{
    __shared__ float As[BK][BM];
    __shared__ float Bs[BK][BN];

    const int bm  = blockIdx.y * BM;
    const int bn  = blockIdx.x * BN;
    const int tid = threadIdx.x;

    // load mapping: 256 threads x float4 = 1024 floats = one 128x8 tile
    const int lrow  = tid >> 1;          // 0..127
    const int lcol4 = (tid & 1) * 4;     // 0 or 4

    // compute mapping: 16x16 thread grid of 8x8 tiles
    const int tm = (tid >> 4) << 3;      // 0..120
    const int tn = (tid & 15) << 3;      // 0..120

    float acc[TM][TN];
#pragma unroll
    for (int i = 0; i < TM; i++)
#pragma unroll
        for (int j = 0; j < TN; j++) acc[i][j] = 0.0f;

    const float* aptr = A + (size_t)(bm + lrow) * H_ + lcol4;
    const bool   bvalid = (bn + lrow) < N;
    const float* bptr = bvalid ? (W + (size_t)(bn + lrow) * H_ + lcol4) : W;

    for (int k0 = 0; k0 < H_; k0 += BK) {
        float4 av = *(const float4*)(aptr + k0);
        float4 bv = make_float4(0.f, 0.f, 0.f, 0.f);
        if (bvalid) bv = *(const float4*)(bptr + k0);

        As[lcol4 + 0][lrow] = av.x;
        As[lcol4 + 1][lrow] = av.y;
        As[lcol4 + 2][lrow] = av.z;
        As[lcol4 + 3][lrow] = av.w;
        Bs[lcol4 + 0][lrow] = bv.x;
        Bs[lcol4 + 1][lrow] = bv.y;
        Bs[lcol4 + 2][lrow] = bv.z;
        Bs[lcol4 + 3][lrow] = bv.w;
        __syncthreads();

#pragma unroll
        for (int k = 0; k < BK; ++k) {
            float ar[TM], br[TN];
            *(float4*)&ar[0] = *(const float4*)&As[k][tm];
            *(float4*)&ar[4] = *(const float4*)&As[k][tm + 4];
            *(float4*)&br[0] = *(const float4*)&Bs[k][tn];
            *(float4*)&br[4] = *(const float4*)&Bs[k][tn + 4];
#pragma unroll
            for (int i = 0; i < TM; i++)
#pragma unroll
                for (int j = 0; j < TN; j++)
                    acc[i][j] = fmaf(ar[i], br[j], acc[i][j]);
        }
        __syncthreads();
    }

#pragma unroll
    for (int i = 0; i < TM; i++) {
        const int gm = bm + tm + i;
        float* zr = g_z + (size_t)gm * NTOT + col_off;
#pragma unroll
        for (int j = 0; j < TN; j++) {
            const int gn = bn + tn + j;
            if (gn < N) zr[gn] = sigmoidf(acc[i][j] + bias[gn]);
        }
    }
}

// ---------------------------------------------------------------------------
// Epilogue helpers: CORRECT block-wide reductions with shared-memory
// broadcast (round-2 bug: warps 1..7 got -inf from a warp-local shuffle).
// ---------------------------------------------------------------------------
__device__ __forceinline__ float warp_max(float v) {
#pragma unroll
    for (int o = 16; o; o >>= 1) v = fmaxf(v, __shfl_xor_sync(0xffffffffu, v, o));
    return v;
}
__device__ __forceinline__ float warp_sum(float v) {
#pragma unroll
    for (int o = 16; o; o >>= 1) v += __shfl_xor_sync(0xffffffffu, v, o);
    return v;
}

// 256-thread block reductions; sred must have >= 9 floats.
__device__ __forceinline__ float block_max_256(float v, float* sred) {
    const int lane = threadIdx.x & 31, wid = threadIdx.x >> 5;
    v = warp_max(v);
    if (lane == 0) sred[wid] = v;
    __syncthreads();
    if (wid == 0) {
        float t = (lane < 8) ? sred[lane] : -INFINITY;
        t = warp_max(t);
        if (lane == 0) sred[8] = t;
    }
    __syncthreads();
    float r = sred[8];
    __syncthreads();
    return r;
}
__device__ __forceinline__ float block_sum_256(float v, float* sred) {
    const int lane = threadIdx.x & 31, wid = threadIdx.x >> 5;
    v = warp_sum(v);
    if (lane == 0) sred[wid] = v;
    __syncthreads();
    if (wid == 0) {
        float t = (lane < 8) ? sred[lane] : 0.f;
        t = warp_sum(t);
        if (lane == 0) sred[8] = t;
    }
    __syncthreads();
    float r = sred[8];
    __syncthreads();
    return r;
}

// ---------------------------------------------------------------------------
// Epilogue: per row b, build logits (path products), write logits3 to out,
// compute the 3-level cross-entropy contribution into g_loss_rows[b].
// ---------------------------------------------------------------------------
__global__ void __launch_bounds__(256)
epilogue_kernel(const int* __restrict__ labels,
                float* __restrict__ out,
                int write_logits)
{
    const int b   = blockIdx.x;
    const int tid = threadIdx.x;

    __shared__ float zs[NTOT];   // whole z-row staged once (12.4 KB)
    __shared__ float sred[9];

    const float* zrow = g_z + (size_t)b * NTOT;
    for (int i = tid; i < NTOT; i += 256) zs[i] = zrow[i];
    __syncthreads();

    const float* z1 = zs;
    const float* z2 = zs + N1_;
    const float* z3 = zs + N1_ + N2_;

    // ---- level 3: logits l3[k] = z3[k/100]*z3[k/10]*z3[k] ----
    float m3 = -INFINITY;
    for (int k = tid; k < N3_; k += 256) {
        float v = z3[k / 100] * z3[k / 10] * z3[k];
        if (write_logits) out[(size_t)b * N3_ + k] = v;
        m3 = fmaxf(m3, v);
    }
    m3 = block_max_256(m3, sred);
    float s3 = 0.f;
    for (int k = tid; k < N3_; k += 256) {
        float v = z3[k / 100] * z3[k / 10] * z3[k];
        s3 += expf(v - m3);
    }
    s3 = block_sum_256(s3, sred);

    // ---- level 2: l2[j] = z2[j/10]*z2[j] ----
    float m2 = -INFINITY;
    for (int j = tid; j < N2_; j += 256)
        m2 = fmaxf(m2, z2[j / 10] * z2[j]);
    m2 = block_max_256(m2, sred);
    float s2 = 0.f;
    for (int j = tid; j < N2_; j += 256)
        s2 += expf(z2[j / 10] * z2[j] - m2);
    s2 = block_sum_256(s2, sred);

    // ---- level 1: l1 = z1 ----
    float m1 = block_max_256((tid < N1_) ? z1[tid] : -INFINITY, sred);
    float s1 = block_sum_256((tid < N1_) ? expf(z1[tid] - m1) : 0.f, sred);

    if (tid == 0) {
        const int lab3 = labels[b];
        const int lab2 = lab3 / 10;
        const int lab1 = lab3 / 100;
        const float l3lab = z3[lab3 / 100] * z3[lab3 / 10] * z3[lab3];
        const float l2lab = z2[lab2 / 10] * z2[lab2];
        const float l1lab = z1[lab1];
        float t = (m3 + logf(s3) - l3lab)
                + (m2 + logf(s2) - l2lab)
                + (m1 + logf(s1) - l1lab);
        g_loss_rows[b] = t;
    }
}

// ---------------------------------------------------------------------------
// Final deterministic reduction of the per-row losses -> loss scalar
// ---------------------------------------------------------------------------
__global__ void __launch_bounds__(1024)
finalize_loss(float* __restrict__ out, int idx)
{
    __shared__ float sred[32];
    const int tid = threadIdx.x;
    float s = 0.f;
    for (int i = tid; i < B_; i += 1024) s += g_loss_rows[i];
    s = warp_sum(s);
    if ((tid & 31) == 0) sred[tid >> 5] = s;
    __syncthreads();
    if (tid < 32) {
        s = warp_sum(sred[tid]);
        if (tid == 0) out[idx] = s / (float)B_;
    }
}

// ---------------------------------------------------------------------------
extern "C" void kernel_launch(void* const* d_in, const int* in_sizes, int n_in,
                              void* d_out, int out_size)
{
    (void)in_sizes; (void)n_in;
    const float* x      = (const float*)d_in[0];
    const int*   labels = (const int*)  d_in[1];
    const float* W1 = (const float*)d_in[2];
    const float* b1 = (const float*)d_in[3];
    const float* W2 = (const float*)d_in[4];
    const float* b2 = (const float*)d_in[5];
    const float* W3 = (const float*)d_in[6];
    const float* b3 = (const float*)d_in[7];

    float* out = (float*)d_out;
    const long long full = (long long)B_ * N3_;
    const int write_logits = ((long long)out_size >= full) ? 1 : 0;
    const int write_loss   = ((long long)out_size != full) ? 1 : 0;
    const int loss_idx     = out_size - 1;  // loss sits in the last element

    dim3 blk(256);
    // level 1: N=28
    gemm_bias_sigmoid<<<dim3(1,  B_ / BM), blk>>>(x, W1, b1, N1_, 0);
    // level 2: N=280
    gemm_bias_sigmoid<<<dim3(3,  B_ / BM), blk>>>(x, W2, b2, N2_, N1_);
    // level 3: N=2800
    gemm_bias_sigmoid<<<dim3(22, B_ / BM), blk>>>(x, W3, b3, N3_, N1_ + N2_);

    epilogue_kernel<<<B_, 256>>>(labels, out, write_logits);

    if (write_loss)
        finalize_loss<<<1, 1024>>>(out, loss_idx);
}

// round 5
// speedup vs baseline: 2.8541x; 2.8541x over previous
#include <cuda_runtime.h>
#include <cuda_bf16.h>
#include <math.h>
#include <stdint.h>

#define B_   4096
#define H_   1024
#define N1_  28
#define N2_  280
#define N3_  2800
#define NTOT (N1_ + N2_ + N3_)   // 3108

// tcgen05 is arch-SPECIFIC: only emit its asm when compiling the sm_103a
// target. The family/base target (compute_103 PTX) compiles empty stubs that
// never run (loader picks the exact-match sm_103a cubin on GB300).
#if defined(__CUDA_ARCH_FEAT_SM103_ALL) || \
    (defined(__CUDA_ARCH_SPECIFIC__) && (__CUDA_ARCH_SPECIFIC__ == 1030))
#define HAS_TCGEN05 1
#endif

// ---------------------------------------------------------------------------
// Device scratch (no allocs allowed): bf16 hi/lo splits, z, loss partials
// ---------------------------------------------------------------------------
__device__ __align__(16) __nv_bfloat16 g_xh[(size_t)B_ * H_];
__device__ __align__(16) __nv_bfloat16 g_xl[(size_t)B_ * H_];
__device__ __align__(16) __nv_bfloat16 g_wh[(size_t)NTOT * H_];
__device__ __align__(16) __nv_bfloat16 g_wl[(size_t)NTOT * H_];
__device__ float g_bias[NTOT];
__device__ float g_z[(size_t)B_ * NTOT];
__device__ float g_loss_rows[B_];

// ---------------------------------------------------------------------------
// PTX helpers — all bodies guarded by HAS_TCGEN05
// ---------------------------------------------------------------------------
__device__ __forceinline__ uint32_t smem_u32(const void* p) {
    uint32_t a;
    asm("{ .reg .u64 t; cvta.to.shared.u64 t, %1; cvt.u32.u64 %0, t; }" : "=r"(a) : "l"(p));
    return a;
}

#ifdef HAS_TCGEN05

__device__ __forceinline__ uint32_t elect_one_pred() {
    uint32_t pred;
    asm volatile("{\n\t.reg .pred p;\n\telect.sync _|p, 0xFFFFFFFF;\n\t"
                 "selp.b32 %0, 1, 0, p;\n\t}" : "=r"(pred));
    return pred;
}
#define TCGEN05_ALLOC(smem_addr, nCols) \
    asm volatile("tcgen05.alloc.cta_group::1.sync.aligned.shared::cta.b32 [%0], %1;" \
                 :: "r"((uint32_t)(smem_addr)), "r"((uint32_t)(nCols)) : "memory")
#define TCGEN05_DEALLOC(tmem_addr, nCols) \
    asm volatile("tcgen05.dealloc.cta_group::1.sync.aligned.b32 %0, %1;" \
                 :: "r"(tmem_addr), "r"((uint32_t)(nCols)))
#define TCGEN05_COMMIT(mbar) \
    asm volatile("tcgen05.commit.cta_group::1.mbarrier::arrive::one.shared::cluster.b64 [%0];" \
                 :: "r"((uint32_t)(mbar)) : "memory")
#define TCGEN05_FENCE_AFTER() asm volatile("tcgen05.fence::after_thread_sync;" ::: "memory")
#define TCGEN05_FENCE_BEFORE() asm volatile("tcgen05.fence::before_thread_sync;" ::: "memory")
#define TCGEN05_WAIT_LD() asm volatile("tcgen05.wait::ld.sync.aligned;" ::: "memory")
#define MBARRIER_INIT(mbar, cnt) \
    asm volatile("mbarrier.init.shared.b64 [%0], %1;" :: "r"((uint32_t)(mbar)), "r"((uint32_t)(cnt)) : "memory")
#define MBARRIER_INVAL(mbar) \
    asm volatile("mbarrier.inval.shared.b64 [%0];" :: "r"((uint32_t)(mbar)) : "memory")
#define FENCE_PROXY_ASYNC() asm volatile("fence.proxy.async.shared::cta;" ::: "memory")

#define MBARRIER_WAIT_PARITY(mbar, parity) do {                                   \
    uint32_t _m = (uint32_t)(mbar); uint32_t _p = (uint32_t)(parity); uint32_t _d; \
    asm volatile("{\n\t.reg .pred p;\n\t"                                         \
        "mbarrier.try_wait.parity.acquire.cta.shared::cta.b64 p, [%1], %2;\n\t"   \
        "selp.b32 %0, 1, 0, p;\n\t}" : "=r"(_d) : "r"(_m), "r"(_p) : "memory");   \
    if (!_d) {                                                                    \
        asm volatile("{\n\t.reg .pred P1;\n\t"                                    \
            "WL_%=:\n\t"                                                          \
            "mbarrier.try_wait.parity.acquire.cta.shared::cta.b64 P1, [%0], %1, 0x989680;\n\t" \
            "@P1 bra.uni WD_%=;\n\t"                                              \
            "bra.uni WL_%=;\n\t"                                                  \
            "WD_%=:\n\t}" :: "r"(_m), "r"(_p) : "memory");                        \
    }                                                                             \
} while (0)

#define LD_TM_X32(r, addr)                                                        \
    asm volatile("tcgen05.ld.sync.aligned.32x32b.x32.b32 "                        \
        "{%0, %1, %2, %3, %4, %5, %6, %7, %8, %9, %10, %11, %12, %13, %14, %15, " \
        " %16, %17, %18, %19, %20, %21, %22, %23, %24, %25, %26, %27, %28, %29, %30, %31}, [%32];" \
        : "=r"((r)[0]),  "=r"((r)[1]),  "=r"((r)[2]),  "=r"((r)[3]),              \
          "=r"((r)[4]),  "=r"((r)[5]),  "=r"((r)[6]),  "=r"((r)[7]),              \
          "=r"((r)[8]),  "=r"((r)[9]),  "=r"((r)[10]), "=r"((r)[11]),             \
          "=r"((r)[12]), "=r"((r)[13]), "=r"((r)[14]), "=r"((r)[15]),             \
          "=r"((r)[16]), "=r"((r)[17]), "=r"((r)[18]), "=r"((r)[19]),             \
          "=r"((r)[20]), "=r"((r)[21]), "=r"((r)[22]), "=r"((r)[23]),             \
          "=r"((r)[24]), "=r"((r)[25]), "=r"((r)[26]), "=r"((r)[27]),             \
          "=r"((r)[28]), "=r"((r)[29]), "=r"((r)[30]), "=r"((r)[31])              \
        : "r"(addr))

// SW128 K-major descriptor (verified constant from examples)
static __device__ __forceinline__ uint64_t make_desc_sw128(uint32_t base) {
    const uint64_t BASE = (uint64_t(2) << 61) | (uint64_t(1) << 46) |
                          (uint64_t(64) << 32) | (uint64_t(1) << 16);
    return BASE | ((uint64_t)(base >> 4) & 0x3FFF);
}

// cta_group::1 kind::f16 SS MMA (bf16 in, fp32 accum)
__device__ __forceinline__ void mma_bf16_ss(uint32_t d, uint64_t a, uint64_t b,
                                            uint32_t idesc, bool acc) {
    uint32_t e = acc ? 1u : 0u;
    asm volatile("{\n\t.reg .pred p;\n\tsetp.ne.u32 p, %5, 0;\n\t"
        "tcgen05.mma.cta_group::1.kind::f16 [%0], %1, %2, %3, {%4, %4, %4, %4}, p;\n\t}"
        :: "r"(d), "l"(a), "l"(b), "r"(idesc), "r"(0u), "r"(e) : "memory");
}

#endif // HAS_TCGEN05

__device__ __forceinline__ uint32_t sw128(uint32_t b) { return b ^ ((b >> 3) & 0x70); }

// idesc: dtype F32, atype/btype BF16, N=128, M=128
#define MMA_IDESC 0x8200490u

// ---------------------------------------------------------------------------
// Conversion: fp32 -> bf16 hi/lo split
// ---------------------------------------------------------------------------
__global__ void __launch_bounds__(256)
convert_split(const float* __restrict__ src, __nv_bfloat16* __restrict__ hi,
              __nv_bfloat16* __restrict__ lo, int n)
{
    for (int i = blockIdx.x * 256 + threadIdx.x; i < n; i += gridDim.x * 256) {
        float v = src[i];
        __nv_bfloat16 h = __float2bfloat16_rn(v);
        hi[i] = h;
        lo[i] = __float2bfloat16_rn(v - __bfloat162float(h));
    }
}

__global__ void __launch_bounds__(1024)
concat_bias(const float* __restrict__ b1, const float* __restrict__ b2,
            const float* __restrict__ b3)
{
    int i = threadIdx.x + blockIdx.x * 1024;
    if (i < N1_) g_bias[i] = b1[i];
    if (i < N2_) g_bias[N1_ + i] = b2[i];
    for (int k = i; k < N3_; k += gridDim.x * 1024) g_bias[N1_ + N2_ + k] = b3[k];
}

// ---------------------------------------------------------------------------
// tcgen05 GEMM: Z = sigmoid(x @ Wcat^T + bias), error-compensated bf16
// Tile: 128 (M) x 128 (N), K chunked by 64. 256 threads.
// ---------------------------------------------------------------------------
#define KC     64
#define NCHUNK (H_ / KC)   // 16
#define SM_AH  1024
#define SM_AL  (SM_AH + 128 * 128)      // 16 KB tiles (128 rows x 128B)
#define SM_BH  (SM_AL + 128 * 128)
#define SM_BL  (SM_BH + 128 * 128)
#define SM_TOT (SM_BL + 128 * 128)      // 66560 B

__global__ void __launch_bounds__(256)
gemm_tc(void)
{
#ifdef HAS_TCGEN05
    extern __shared__ char smem[];
    const uint32_t sb  = smem_u32(smem);
    const int tid  = threadIdx.x;
    const int wid  = tid >> 5;
    const int lane = tid & 31;
    const int bm = blockIdx.y * 128;
    const int bn = blockIdx.x * 128;

    if (wid == 0) TCGEN05_ALLOC(sb + 0, 128);
    if (tid == 0) MBARRIER_INIT(sb + 8, 1);
    __syncthreads();
    uint32_t tmem;
    asm volatile("ld.shared.b32 %0, [%1];" : "=r"(tmem) : "r"(sb + 0));

    const uint64_t dAH = make_desc_sw128(sb + SM_AH);
    const uint64_t dAL = make_desc_sw128(sb + SM_AL);
    const uint64_t dBH = make_desc_sw128(sb + SM_BH);
    const uint64_t dBL = make_desc_sw128(sb + SM_BL);

    // per-thread load mapping: 4 passes x 8 bf16 (16B) per operand tile
    int phase = 0;
    for (int c = 0; c < NCHUNK; ++c) {
        if (c > 0) {            // previous chunk's MMAs must finish before overwrite
            MBARRIER_WAIT_PARITY(sb + 8, phase);
            phase ^= 1;
        }
#pragma unroll
        for (int p = 0; p < 4; ++p) {
            const int e   = (tid + 256 * p) * 8;   // element index in 128x64 tile
            const int row = e >> 6;
            const int col = e & 63;
            const uint32_t so = sw128((uint32_t)(row * 128 + col * 2));
            const size_t aoff = (size_t)(bm + row) * H_ + c * KC + col;
            *(uint4*)(smem + SM_AH + so) = *(const uint4*)(g_xh + aoff);
            *(uint4*)(smem + SM_AL + so) = *(const uint4*)(g_xl + aoff);
            const int n = bn + row;
            if (n < NTOT) {
                const size_t boff = (size_t)n * H_ + c * KC + col;
                *(uint4*)(smem + SM_BH + so) = *(const uint4*)(g_wh + boff);
                *(uint4*)(smem + SM_BL + so) = *(const uint4*)(g_wl + boff);
            } else {
                const uint4 z = make_uint4(0, 0, 0, 0);
                *(uint4*)(smem + SM_BH + so) = z;
                *(uint4*)(smem + SM_BL + so) = z;
            }
        }
        FENCE_PROXY_ASYNC();
        __syncthreads();

        if (wid == 0 && elect_one_pred()) {
#pragma unroll
            for (int ks = 0; ks < 4; ++ks) {       // K=16 per MMA -> 4 steps
                const uint64_t o = (uint64_t)(ks * 2);
                mma_bf16_ss(tmem, dAH + o, dBH + o, MMA_IDESC, !(c == 0 && ks == 0));
                mma_bf16_ss(tmem, dAH + o, dBL + o, MMA_IDESC, true);
                mma_bf16_ss(tmem, dAL + o, dBH + o, MMA_IDESC, true);
            }
            TCGEN05_COMMIT(sb + 8);
        }
        __syncthreads();
    }

    MBARRIER_WAIT_PARITY(sb + 8, phase);
    TCGEN05_FENCE_AFTER();

    // Epilogue: bias + sigmoid, write z. Warps 0-3 read their TMEM subpartition.
    if (wid < 4) {
        const int row = bm + wid * 32 + lane;
        float* zr = g_z + (size_t)row * NTOT;
#pragma unroll
        for (int g = 0; g < 4; ++g) {
            uint32_t r[32];
            LD_TM_X32(r, tmem + g * 32);
            TCGEN05_WAIT_LD();
#pragma unroll
            for (int j = 0; j < 32; ++j) {
                const int col = bn + g * 32 + j;
                if (col < NTOT) {
                    float v = __uint_as_float(r[j]) + g_bias[col];
                    zr[col] = 1.0f / (1.0f + expf(-v));
                }
            }
        }
    }
    TCGEN05_FENCE_BEFORE();
    __syncthreads();
    if (wid == 0) {
        if (elect_one_pred()) MBARRIER_INVAL(sb + 8);
        TCGEN05_DEALLOC(tmem, 128);
    }
#endif // HAS_TCGEN05
}

// ---------------------------------------------------------------------------
// CE epilogue (unchanged from passing round 3)
// ---------------------------------------------------------------------------
__device__ __forceinline__ float warp_max(float v) {
#pragma unroll
    for (int o = 16; o; o >>= 1) v = fmaxf(v, __shfl_xor_sync(0xffffffffu, v, o));
    return v;
}
__device__ __forceinline__ float warp_sum(float v) {
#pragma unroll
    for (int o = 16; o; o >>= 1) v += __shfl_xor_sync(0xffffffffu, v, o);
    return v;
}
__device__ __forceinline__ float block_max_256(float v, float* sred) {
    const int lane = threadIdx.x & 31, wid = threadIdx.x >> 5;
    v = warp_max(v);
    if (lane == 0) sred[wid] = v;
    __syncthreads();
    if (wid == 0) {
        float t = (lane < 8) ? sred[lane] : -INFINITY;
        t = warp_max(t);
        if (lane == 0) sred[8] = t;
    }
    __syncthreads();
    float r = sred[8];
    __syncthreads();
    return r;
}
__device__ __forceinline__ float block_sum_256(float v, float* sred) {
    const int lane = threadIdx.x & 31, wid = threadIdx.x >> 5;
    v = warp_sum(v);
    if (lane == 0) sred[wid] = v;
    __syncthreads();
    if (wid == 0) {
        float t = (lane < 8) ? sred[lane] : 0.f;
        t = warp_sum(t);
        if (lane == 0) sred[8] = t;
    }
    __syncthreads();
    float r = sred[8];
    __syncthreads();
    return r;
}

__global__ void __launch_bounds__(256)
epilogue_kernel(const int* __restrict__ labels,
                float* __restrict__ out,
                int write_logits)
{
    const int b   = blockIdx.x;
    const int tid = threadIdx.x;

    __shared__ float zs[NTOT];
    __shared__ float sred[9];

    const float* zrow = g_z + (size_t)b * NTOT;
    for (int i = tid; i < NTOT; i += 256) zs[i] = zrow[i];
    __syncthreads();

    const float* z1 = zs;
    const float* z2 = zs + N1_;
    const float* z3 = zs + N1_ + N2_;

    float m3 = -INFINITY;
    for (int k = tid; k < N3_; k += 256) {
        float v = z3[k / 100] * z3[k / 10] * z3[k];
        if (write_logits) out[(size_t)b * N3_ + k] = v;
        m3 = fmaxf(m3, v);
    }
    m3 = block_max_256(m3, sred);
    float s3 = 0.f;
    for (int k = tid; k < N3_; k += 256)
        s3 += expf(z3[k / 100] * z3[k / 10] * z3[k] - m3);
    s3 = block_sum_256(s3, sred);

    float m2 = -INFINITY;
    for (int j = tid; j < N2_; j += 256)
        m2 = fmaxf(m2, z2[j / 10] * z2[j]);
    m2 = block_max_256(m2, sred);
    float s2 = 0.f;
    for (int j = tid; j < N2_; j += 256)
        s2 += expf(z2[j / 10] * z2[j] - m2);
    s2 = block_sum_256(s2, sred);

    float m1 = block_max_256((tid < N1_) ? z1[tid] : -INFINITY, sred);
    float s1 = block_sum_256((tid < N1_) ? expf(z1[tid] - m1) : 0.f, sred);

    if (tid == 0) {
        const int lab3 = labels[b];
        const int lab2 = lab3 / 10;
        const int lab1 = lab3 / 100;
        const float l3lab = z3[lab3 / 100] * z3[lab3 / 10] * z3[lab3];
        const float l2lab = z2[lab2 / 10] * z2[lab2];
        const float l1lab = z1[lab1];
        g_loss_rows[b] = (m3 + logf(s3) - l3lab)
                       + (m2 + logf(s2) - l2lab)
                       + (m1 + logf(s1) - l1lab);
    }
}

__global__ void __launch_bounds__(1024)
finalize_loss(float* __restrict__ out, int idx)
{
    __shared__ float sred[32];
    const int tid = threadIdx.x;
    float s = 0.f;
    for (int i = tid; i < B_; i += 1024) s += g_loss_rows[i];
    s = warp_sum(s);
    if ((tid & 31) == 0) sred[tid >> 5] = s;
    __syncthreads();
    if (tid < 32) {
        s = warp_sum(sred[tid]);
        if (tid == 0) out[idx] = s / (float)B_;
    }
}

// ---------------------------------------------------------------------------
extern "C" void kernel_launch(void* const* d_in, const int* in_sizes, int n_in,
                              void* d_out, int out_size)
{
    (void)in_sizes; (void)n_in;
    const float* x      = (const float*)d_in[0];
    const int*   labels = (const int*)  d_in[1];
    const float* W1 = (const float*)d_in[2];
    const float* b1 = (const float*)d_in[3];
    const float* W2 = (const float*)d_in[4];
    const float* b2 = (const float*)d_in[5];
    const float* W3 = (const float*)d_in[6];
    const float* b3 = (const float*)d_in[7];

    float* out = (float*)d_out;
    const long long full = (long long)B_ * N3_;
    const int write_logits = ((long long)out_size >= full) ? 1 : 0;
    const int write_loss   = ((long long)out_size != full) ? 1 : 0;
    const int loss_idx     = out_size - 1;

    static int smem_set = 0;
    if (!smem_set) {
        cudaFuncSetAttribute(gemm_tc, cudaFuncAttributeMaxDynamicSharedMemorySize, SM_TOT);
        smem_set = 1;
    }

    __nv_bfloat16 *xh, *xl, *wh, *wl;
    cudaGetSymbolAddress((void**)&xh, g_xh);
    cudaGetSymbolAddress((void**)&xl, g_xl);
    cudaGetSymbolAddress((void**)&wh, g_wh);
    cudaGetSymbolAddress((void**)&wl, g_wl);

    convert_split<<<1024, 256>>>(x,  xh, xl, B_ * H_);
    convert_split<<<128,  256>>>(W1, wh,                    wl,                    N1_ * H_);
    convert_split<<<256,  256>>>(W2, wh + (size_t)N1_ * H_, wl + (size_t)N1_ * H_, N2_ * H_);
    convert_split<<<1024, 256>>>(W3, wh + (size_t)(N1_ + N2_) * H_,
                                     wl + (size_t)(N1_ + N2_) * H_, N3_ * H_);
    concat_bias<<<3, 1024>>>(b1, b2, b3);

    dim3 grid((NTOT + 127) / 128, B_ / 128);   // 25 x 32
    gemm_tc<<<grid, 256, SM_TOT>>>();

    epilogue_kernel<<<B_, 256>>>(labels, out, write_logits);
    if (write_loss)
        finalize_loss<<<1, 1024>>>(out, loss_idx);
}